// round 15
// baseline (speedup 1.0000x reference)
#include <cuda_runtime.h>
#include <cuda_bf16.h>

// Problem constants (fixed by setup_inputs)
#define BB 8
#define T1 256
#define T2 1024
#define CC 128
#define NDIAG (T1 + T2 - 1)   // 1279

#define BIGF 10000000.0f
#define WPF  1.0f

// Phase-1 tiling (R12/R14 version — measured 27us, near fma-pipe roofline)
#define TJ 64
#define TI 128
#define KC 16

// Phase-2: 3 warps, 3 cols/thread, halo = 2 threads (6 cols), superstep = 6 diags
#define NW3 3
#define DTW_THREADS 96
#define SS 6                  // diags per superstep

// Scratch (allocation-free rule: __device__ globals)
__device__ float g_cost[BB * T1 * T2];   // [b][j][i]
__device__ float g_loss[BB];

// ---------------------------------------------------------------------------
// Phase 1: cost[b][j][i] = mean_c |A[b][j][c] - B[b][i][c]|  (unchanged)
// ---------------------------------------------------------------------------
__global__ __launch_bounds__(256) void cost_kernel(const float* __restrict__ A,
                                                   const float* __restrict__ Bf) {
    __shared__ float As[KC][TJ + 4];   // [k][j]
    __shared__ float Bs[KC][TI + 4];   // [k][i]

    const int b  = blockIdx.z;
    const int jb = blockIdx.y * TJ;
    const int ib = blockIdx.x * TI;
    const int tid = threadIdx.x;

    const int kl = tid & 15;
    const int rl = tid >> 4;

    const int tx = tid & 15;
    const int ty = tid >> 4;
    const int j0 = ty * 4;
    const int ia = tx * 4;
    const int ib2 = 64 + tx * 4;

    const float* Ag = A + (size_t)(b * T1 + jb) * CC;
    const float* Bg = Bf + (size_t)(b * T2 + ib) * CC;

    float acc[4][8];
#pragma unroll
    for (int u = 0; u < 4; u++)
#pragma unroll
        for (int v = 0; v < 8; v++) acc[u][v] = 0.0f;

    for (int c0 = 0; c0 < CC; c0 += KC) {
#pragma unroll
        for (int p = 0; p < 4; p++) {
            int jj = rl + p * 16;
            As[kl][jj] = Ag[jj * CC + c0 + kl];
        }
#pragma unroll
        for (int p = 0; p < 8; p++) {
            int ii = rl + p * 16;
            Bs[kl][ii] = Bg[ii * CC + c0 + kl];
        }
        __syncthreads();

#pragma unroll
        for (int kk = 0; kk < KC; kk++) {
            float4 a4 = *(const float4*)&As[kk][j0];
            float4 b0 = *(const float4*)&Bs[kk][ia];
            float4 b1 = *(const float4*)&Bs[kk][ib2];
            float av[4] = {a4.x, a4.y, a4.z, a4.w};
            float bv[8] = {b0.x, b0.y, b0.z, b0.w, b1.x, b1.y, b1.z, b1.w};
#pragma unroll
            for (int u = 0; u < 4; u++)
#pragma unroll
                for (int v = 0; v < 8; v++)
                    acc[u][v] += fabsf(av[u] - bv[v]);
        }
        __syncthreads();
    }

    const float sc = 1.0f / (float)CC;
#pragma unroll
    for (int u = 0; u < 4; u++) {
        float* dst = g_cost + (size_t)((b * T1 + jb + j0 + u) * T2) + ib;
        float4 o0 = make_float4(acc[u][0] * sc, acc[u][1] * sc, acc[u][2] * sc, acc[u][3] * sc);
        float4 o1 = make_float4(acc[u][4] * sc, acc[u][5] * sc, acc[u][6] * sc, acc[u][7] * sc);
        *(float4*)(dst + ia)  = o0;
        *(float4*)(dst + ib2) = o1;
    }
}

// ---------------------------------------------------------------------------
// Phase 2: 3-cols-per-thread wavefront, 3 warps (one per SMSP).
//   Thread (warp w, lane l) owns cols base+3l+{0,1,2}, base = 90w - 6.
//   Per diag: cells B,C use only own registers; cell A uses one shfl of the
//   neighbor's C. Halo = lanes 0,1 (6 cols), refreshed every 6 diags via a
//   single __syncthreads + 6-float state publish from lanes 30,31.
// ---------------------------------------------------------------------------
__device__ __forceinline__ float ex2f(float x) {
    float r; asm("ex2.approx.ftz.f32 %0, %1;" : "=f"(r) : "f"(x)); return r;
}
__device__ __forceinline__ float lg2f(float x) {
    float r; asm("lg2.approx.ftz.f32 %0, %1;" : "=f"(r) : "f"(x)); return r;
}

#define KLOG2E 144.26950408889634f        // 100 * log2(e)
#define TLN2   0.0069314718055994531f     // 0.01 * ln(2)

__device__ __forceinline__ float ldc_clamped(const float* __restrict__ row, int i) {
    i = min(max(i, 0), T2 - 1);
    return __ldg(row + i);
}

// softmin core: given lprev(v0), cur(v1 base), lcur(v2 base), cost -> new value
__device__ __forceinline__ float cell_step(float lprev, float cur, float lcur, float cd) {
    float v1 = cur + WPF;
    float mn_a = fminf(lprev, v1);
    float mx_a = fmaxf(lprev, v1);
    float v2 = lcur + WPF;
    float m   = fminf(mn_a, v2);
    float oth = fmaxf(mn_a, v2);
    float e1 = ex2f((m - mx_a) * KLOG2E);
    float e2 = ex2f((m - oth)  * KLOG2E);
    float s = 1.0f + (e1 + e2);
    return cd + fmaf(-TLN2, lg2f(s), m);
}

__global__ __launch_bounds__(DTW_THREADS) void dtw_kernel(const int* __restrict__ len_a,
                                                          const int* __restrict__ len_b) {
    const int b    = blockIdx.x;
    const int tid  = threadIdx.x;
    const int warp = tid >> 5;
    const int lane = tid & 31;

    const int colA = 90 * warp - 6 + 3 * lane;   // -6 .. 267
    const int colB = colA + 1;
    const int colC = colA + 2;

    __shared__ float pub[2][2][2][8];            // [parity][producer warp][lane-30][state]

    const float* __restrict__ crowA = g_cost + (size_t)(b * T1 + min(max(colA, 0), T1 - 1)) * T2;
    const float* __restrict__ crowB = g_cost + (size_t)(b * T1 + min(max(colB, 0), T1 - 1)) * T2;
    const float* __restrict__ crowC = g_cost + (size_t)(b * T1 + min(max(colC, 0), T1 - 1)) * T2;

    const int la = len_a[b];
    const int lb = len_b[b];
    const int dtarget = la + lb - 2;             // <= 1278
    const bool owner = (lane >= 2);
    const bool wrA = owner && (colA == la - 1);
    const bool wrB = owner && (colB == la - 1);
    const bool wrC = owner && (colC == la - 1);
    const bool w0  = (warp == 0);
    const bool prodlane = (lane >= 30) && (warp < 2);
    const bool conslane = (lane < 2) && (warp > 0);

    // State: cur* = diag d-1 values; prevA/prevB = diag d-2 values of A/B;
    // prevShfl = neighbor C at diag d-2 (serves as lprev for cell A).
    float curA = BIGF, curB = BIGF, curC = BIGF;     // pc0: all BIG
    float prevA = BIGF, prevB = BIGF;                // pcp0 (cols != 0 are BIG)
    float prevShfl = (colA == 0) ? 0.0f : BIGF;      // pcp0[0] = 0 feeds col 0's v0

    float resv = 0.0f;

    // Prime cost pipeline for diags 0..5
    float ca[SS], cb[SS], cc[SS];
#pragma unroll
    for (int q = 0; q < SS; q++) {
        ca[q] = ldc_clamped(crowA, q - colA);
        cb[q] = ldc_clamped(crowB, q - colB);
        cc[q] = ldc_clamped(crowC, q - colC);
    }

    int d = 0;
    const int nss = dtarget / SS + 1;

#define STEP3(CA, CB, CC) do {                                               \
        float shin = __shfl_up_sync(0xffffffffu, curC, 1);                   \
        float nA = cell_step(prevShfl, curA, shin, (CA));                    \
        float nB = cell_step(prevA,    curB, curA, (CB));                    \
        float nC = cell_step(prevB,    curC, curB, (CC));                    \
        if (w0) {  /* pin cols < 0 to the BIG boundary (warp-uniform) */     \
            nA = (colA >= 0) ? nA : BIGF;                                    \
            nB = (colB >= 0) ? nB : BIGF;                                    \
            nC = (colC >= 0) ? nC : BIGF;                                    \
        }                                                                    \
        if (d == dtarget) {                                                  \
            if (wrA) resv = nA;                                              \
            if (wrB) resv = nB;                                              \
            if (wrC) resv = nC;                                              \
        }                                                                    \
        prevShfl = shin; prevA = curA; prevB = curB;                         \
        curA = nA; curB = nB; curC = nC;                                     \
        d++;                                                                 \
    } while (0)

    for (int ss = 0; ss < nss; ss++) {
        // Prefetch next superstep's costs (i = d+6+q - col)
        float na[SS], nb[SS], nc[SS];
        int ip = d + SS;
#pragma unroll
        for (int q = 0; q < SS; q++) {
            na[q] = ldc_clamped(crowA, ip + q - colA);
            nb[q] = ldc_clamped(crowB, ip + q - colB);
            nc[q] = ldc_clamped(crowC, ip + q - colC);
        }

        STEP3(ca[0], cb[0], cc[0]);
        STEP3(ca[1], cb[1], cc[1]);
        STEP3(ca[2], cb[2], cc[2]);
        STEP3(ca[3], cb[3], cc[3]);
        STEP3(ca[4], cb[4], cc[4]);
        STEP3(ca[5], cb[5], cc[5]);

#pragma unroll
        for (int q = 0; q < SS; q++) { ca[q] = na[q]; cb[q] = nb[q]; cc[q] = nc[q]; }

        // Publish boundary state (lanes 30,31 of warps 0,1)
        if (prodlane) {
            float* p = pub[ss & 1][warp][lane - 30];
            p[0] = curA; p[1] = curB; p[2] = curC;
            p[3] = prevA; p[4] = prevB; p[5] = prevShfl;
        }
        __syncthreads();
        // Refresh halo (lanes 0,1 of warps 1,2)
        if (conslane) {
            const float* p = pub[ss & 1][warp - 1][lane];
            curA = p[0]; curB = p[1]; curC = p[2];
            prevA = p[3]; prevB = p[4]; prevShfl = p[5];
        }
    }
#undef STEP3

    if (wrA || wrB || wrC) g_loss[b] = resv;
}

// ---------------------------------------------------------------------------
// Phase 3: deterministic fixed-order reduction of the 8 per-batch losses.
// ---------------------------------------------------------------------------
__global__ void reduce_kernel(float* __restrict__ out) {
    float s = 0.0f;
#pragma unroll
    for (int i = 0; i < BB; i++) s += g_loss[i];
    out[0] = s;
}

// ---------------------------------------------------------------------------
extern "C" void kernel_launch(void* const* d_in, const int* in_sizes, int n_in,
                              void* d_out, int out_size) {
    (void)in_sizes; (void)n_in; (void)out_size;
    const float* fa = (const float*)d_in[0];   // fea_a  [8,256,128] f32
    const int*   la = (const int*)  d_in[1];   // len_a  [8] i32
    const float* fb = (const float*)d_in[2];   // fea_b  [8,1024,128] f32
    const int*   lb = (const int*)  d_in[3];   // len_b  [8] i32

    dim3 g1(T2 / TI, T1 / TJ, BB);             // (8,4,8) = 256 blocks
    cost_kernel<<<g1, 256>>>(fa, fb);
    dtw_kernel<<<BB, DTW_THREADS>>>(la, lb);
    reduce_kernel<<<1, 1>>>((float*)d_out);
}

// round 16
// speedup vs baseline: 1.2414x; 1.2414x over previous
#include <cuda_runtime.h>
#include <cuda_bf16.h>

// Problem constants (fixed by setup_inputs)
#define BB 8
#define T1 256
#define T2 1024
#define CC 128
#define NDIAG (T1 + T2 - 1)   // 1279

#define BIGF 10000000.0f
#define WPF  1.0f

// Phase-1 tiling (measured 27us, near fma-pipe roofline)
#define TJ 64
#define TI 128
#define KC 16

// Phase-2 halo wavefront: 10 warps, halo 6, superstep 6 diags, 26 owned cols/warp
#define NW 10
#define DTW_THREADS (NW * 32) // 320
#define HALO 6
#define OWN 26
#define SS 6

#define KLOG2E 144.26950408889634f        // 100 * log2(e)
#define TLN2   0.0069314718055994531f     // 0.01 * ln(2)

// Scratch (allocation-free rule: __device__ globals)
__device__ float g_cost[BB * T1 * T2];   // [b][j][i]
__device__ float g_loss[BB];

// ---------------------------------------------------------------------------
// Phase 1: cost[b][j][i] = mean_c |A[b][j][c] - B[b][i][c]|  (R14 verbatim)
// ---------------------------------------------------------------------------
__global__ __launch_bounds__(256) void cost_kernel(const float* __restrict__ A,
                                                   const float* __restrict__ Bf) {
    __shared__ float As[KC][TJ + 4];   // [k][j]
    __shared__ float Bs[KC][TI + 4];   // [k][i]

    const int b  = blockIdx.z;
    const int jb = blockIdx.y * TJ;
    const int ib = blockIdx.x * TI;
    const int tid = threadIdx.x;

    const int kl = tid & 15;
    const int rl = tid >> 4;

    const int tx = tid & 15;
    const int ty = tid >> 4;
    const int j0 = ty * 4;
    const int ia = tx * 4;
    const int ib2 = 64 + tx * 4;

    const float* Ag = A + (size_t)(b * T1 + jb) * CC;
    const float* Bg = Bf + (size_t)(b * T2 + ib) * CC;

    float acc[4][8];
#pragma unroll
    for (int u = 0; u < 4; u++)
#pragma unroll
        for (int v = 0; v < 8; v++) acc[u][v] = 0.0f;

    for (int c0 = 0; c0 < CC; c0 += KC) {
#pragma unroll
        for (int p = 0; p < 4; p++) {
            int jj = rl + p * 16;
            As[kl][jj] = Ag[jj * CC + c0 + kl];
        }
#pragma unroll
        for (int p = 0; p < 8; p++) {
            int ii = rl + p * 16;
            Bs[kl][ii] = Bg[ii * CC + c0 + kl];
        }
        __syncthreads();

#pragma unroll
        for (int kk = 0; kk < KC; kk++) {
            float4 a4 = *(const float4*)&As[kk][j0];
            float4 b0 = *(const float4*)&Bs[kk][ia];
            float4 b1 = *(const float4*)&Bs[kk][ib2];
            float av[4] = {a4.x, a4.y, a4.z, a4.w};
            float bv[8] = {b0.x, b0.y, b0.z, b0.w, b1.x, b1.y, b1.z, b1.w};
#pragma unroll
            for (int u = 0; u < 4; u++)
#pragma unroll
                for (int v = 0; v < 8; v++)
                    acc[u][v] += fabsf(av[u] - bv[v]);
        }
        __syncthreads();
    }

    const float sc = 1.0f / (float)CC;
#pragma unroll
    for (int u = 0; u < 4; u++) {
        float* dst = g_cost + (size_t)((b * T1 + jb + j0 + u) * T2) + ib;
        float4 o0 = make_float4(acc[u][0] * sc, acc[u][1] * sc, acc[u][2] * sc, acc[u][3] * sc);
        float4 o1 = make_float4(acc[u][4] * sc, acc[u][5] * sc, acc[u][6] * sc, acc[u][7] * sc);
        *(float4*)(dst + ia)  = o0;
        *(float4*)(dst + ib2) = o1;
    }
}

// ---------------------------------------------------------------------------
// Phase 2: halo wavefront with shortened post-shfl chain.
//   col = 26*warp - 6 + lane.  Lanes 0-5: halo (redundant), 6-31: owned.
//   Softmin: with {v0,v1} from own registers, precompute (in the shfl shadow)
//     mn_a,mx_a, e_pre = 2^(K(mn_a-mx_a)), c1 = 1+e_pre, Kmn = K*mn_a.
//   Post-shfl: q = K*mn_a - K*v2;  r = 2^(-|q|);
//     q<=0 (m=mn_a): s = c1 + r
//     q>0  (m=v2):   s = 1 + r + e_pre*r = fma(r, c1, 1)   [exact identity]
//   nv = fma(-t*ln2, lg2(s), m + cd).
// ---------------------------------------------------------------------------
__device__ __forceinline__ float ex2f(float x) {
    float r; asm("ex2.approx.ftz.f32 %0, %1;" : "=f"(r) : "f"(x)); return r;
}
__device__ __forceinline__ float lg2f(float x) {
    float r; asm("lg2.approx.ftz.f32 %0, %1;" : "=f"(r) : "f"(x)); return r;
}

__device__ __forceinline__ float ldc_clamped(const float* __restrict__ row, int i) {
    i = min(max(i, 0), T2 - 1);
    return __ldg(row + i);
}

__global__ __launch_bounds__(DTW_THREADS) void dtw_kernel(const int* __restrict__ len_a,
                                                          const int* __restrict__ len_b) {
    const int b    = blockIdx.x;
    const int tid  = threadIdx.x;
    const int warp = tid >> 5;
    const int lane = tid & 31;
    const int col  = OWN * warp - HALO + lane;     // -6 .. 259

    __shared__ float2 pub[2][NW - 1][HALO];        // [parity][producer warp][halo lane]

    const int colc = min(max(col, 0), T1 - 1);     // clamp for memory only
    const float* __restrict__ crow = g_cost + (size_t)(b * T1 + colc) * T2;

    const int la = len_a[b];
    const int lb = len_b[b];
    const int dtarget = la + lb - 2;               // <= 1278
    const bool wr = (lane >= HALO) && (col == la - 1);  // unique owned writer
    const bool w0 = (warp == 0);

    float cur   = BIGF;                            // pc0: all BIG
    float lprev = (col == 0) ? 0.0f : BIGF;        // pcp0: 0 at position 0
    float resv  = 0.0f;

    // Prime SS-deep cost prefetch (i = d - col, clamped exactly like reference)
    float cd[SS], nx[SS];
#pragma unroll
    for (int q = 0; q < SS; q++) cd[q] = ldc_clamped(crow, q - col);

    int d = 0;
    const int nss = dtarget / SS + 1;

#define STEP(CD) do {                                                        \
        float shin = __shfl_up_sync(0xffffffffu, cur, 1);  /* lane0: halo */ \
        /* off-chain (shfl shadow): */                                       \
        float v1   = cur + WPF;                                              \
        float mn_a = fminf(lprev, v1);                                       \
        float mx_a = fmaxf(lprev, v1);                                       \
        float e_pre = ex2f((mn_a - mx_a) * KLOG2E);                          \
        float c1   = 1.0f + e_pre;                                           \
        float Kmn  = mn_a * KLOG2E;                                          \
        /* on-chain: */                                                      \
        float v2 = shin + WPF;                                               \
        float qv = fmaf(-KLOG2E, v2, Kmn);                                   \
        float r  = ex2f(fminf(qv, -qv));                                     \
        float m  = fminf(mn_a, v2);                                          \
        float mcd = m + (CD);                                                \
        float s1 = c1 + r;                                                   \
        float s2 = fmaf(r, c1, 1.0f);                                        \
        float s  = (qv <= 0.0f) ? s1 : s2;                                   \
        float nv = fmaf(-TLN2, lg2f(s), mcd);                                \
        if (w0) nv = (col >= 0) ? nv : BIGF;   /* pin virtual boundary */    \
        if (wr && d == dtarget) resv = nv;                                   \
        lprev = shin; cur = nv;                                              \
        d++;                                                                 \
    } while (0)

    for (int ss = 0; ss < nss; ss++) {
        // Prefetch next superstep's costs
        int ip = d + SS - col;
#pragma unroll
        for (int q = 0; q < SS; q++) nx[q] = ldc_clamped(crow, ip + q);

        STEP(cd[0]); STEP(cd[1]); STEP(cd[2]);
        STEP(cd[3]); STEP(cd[4]); STEP(cd[5]);

#pragma unroll
        for (int q = 0; q < SS; q++) cd[q] = nx[q];

        // Boundary exchange: one barrier per 6 diagonals, parity-buffered.
        if (lane >= 32 - HALO && warp < NW - 1)
            pub[ss & 1][warp][lane - (32 - HALO)] = make_float2(cur, lprev);
        __syncthreads();
        if (lane < HALO && warp > 0) {
            float2 t = pub[ss & 1][warp - 1][lane];
            cur = t.x; lprev = t.y;
        }
    }
#undef STEP

    if (wr) g_loss[b] = resv;
}

// ---------------------------------------------------------------------------
// Phase 3: deterministic fixed-order reduction of the 8 per-batch losses.
// ---------------------------------------------------------------------------
__global__ void reduce_kernel(float* __restrict__ out) {
    float s = 0.0f;
#pragma unroll
    for (int i = 0; i < BB; i++) s += g_loss[i];
    out[0] = s;
}

// ---------------------------------------------------------------------------
extern "C" void kernel_launch(void* const* d_in, const int* in_sizes, int n_in,
                              void* d_out, int out_size) {
    (void)in_sizes; (void)n_in; (void)out_size;
    const float* fa = (const float*)d_in[0];   // fea_a  [8,256,128] f32
    const int*   la = (const int*)  d_in[1];   // len_a  [8] i32
    const float* fb = (const float*)d_in[2];   // fea_b  [8,1024,128] f32
    const int*   lb = (const int*)  d_in[3];   // len_b  [8] i32

    dim3 g1(T2 / TI, T1 / TJ, BB);             // (8,4,8) = 256 blocks
    cost_kernel<<<g1, 256>>>(fa, fb);
    dtw_kernel<<<BB, DTW_THREADS>>>(la, lb);
    reduce_kernel<<<1, 1>>>((float*)d_out);
}